// round 12
// baseline (speedup 1.0000x reference)
#include <cuda_runtime.h>
#include <math.h>
#include <stdint.h>

// Problem constants
#define D_MODEL 1024
#define N_HEADS 16
#define HD      64
#define BATCH   4
#define SEQ     2048
#define BH      (BATCH * N_HEADS)   // 64
#define M_TOK   (BATCH * SEQ)       // 8192

// Scratch (device globals: allocation-free per harness rules)
__device__ float    g_Q[(size_t)BH * SEQ * HD];
__device__ float    g_K[(size_t)BH * SEQ * HD];
__device__ float    g_V[(size_t)BH * SEQ * HD];
__device__ uint32_t g_Xp[(size_t)M_TOK * D_MODEL];        // x, packed tf32 A-frag
__device__ uint32_t g_Yp[(size_t)M_TOK * D_MODEL];        // attn out, packed tf32 A-frag
__device__ uint32_t g_Wpa[(size_t)3 * D_MODEL * D_MODEL]; // W_attn^T packed tf32 B-frag
__device__ uint32_t g_Wpp[(size_t)D_MODEL * D_MODEL];     // W_proj^T packed tf32 B-frag
__device__ uint32_t g_Qp[(size_t)BH * SEQ * HD];          // Q packed tf32 A-frag (scaled)
__device__ uint32_t g_Kp[(size_t)BH * SEQ * HD];          // K packed tf32 B-frag
__device__ uint32_t g_Vp[(size_t)BH * SEQ * HD];          // V packed tf32 B-frag (n=d)

// ---------------------------------------------------------------------------
// Helpers (base-target ISA; sm_80+)
// ---------------------------------------------------------------------------
__device__ __forceinline__ uint32_t f2tf32(float f) {
    uint32_t r;
    asm("cvt.rna.tf32.f32 %0, %1;" : "=r"(r) : "f"(f));
    return r;
}
__device__ __forceinline__ void mma_tf32(float d[4], const uint32_t a[4],
                                         const uint32_t b[2]) {
    asm volatile(
        "mma.sync.aligned.m16n8k8.row.col.f32.tf32.tf32.f32 "
        "{%0,%1,%2,%3}, {%4,%5,%6,%7}, {%8,%9}, {%0,%1,%2,%3};"
        : "+f"(d[0]), "+f"(d[1]), "+f"(d[2]), "+f"(d[3])
        : "r"(a[0]), "r"(a[1]), "r"(a[2]), "r"(a[3]), "r"(b[0]), "r"(b[1]));
}
__device__ __forceinline__ uint32_t smem_u32(const void* p) {
    uint32_t a;
    asm("{ .reg .u64 t; cvta.to.shared.u64 t, %1; cvt.u32.u64 %0, t; }"
        : "=r"(a) : "l"(p));
    return a;
}
#define CP16(dst, src) \
    asm volatile("cp.async.cg.shared.global [%0], [%1], 16;" \
                 :: "r"(dst), "l"(src) : "memory")
#define CPCOMMIT() asm volatile("cp.async.commit_group;" ::: "memory")
#define CPWAIT1()  asm volatile("cp.async.wait_group 1;" ::: "memory")
#define CPWAIT0()  asm volatile("cp.async.wait_group 0;" ::: "memory")

// ---------------------------------------------------------------------------
// GEMM packing kernels (unchanged).
// ---------------------------------------------------------------------------
__global__ void pack_a(const float* __restrict__ X, uint32_t* __restrict__ Xp)
{
    const int i    = blockIdx.x * 256 + threadIdx.x;   // uint4 index
    const int lane = i & 31, kc = (i >> 5) & 3, slab = (i >> 7) & 31, mb = i >> 12;
    const int g = lane >> 2, t = lane & 3;
    const float* p = X + ((size_t)(mb * 16 + g)) * D_MODEL + slab * 32 + kc * 8 + t;
    uint4 o;
    o.x = f2tf32(p[0]);
    o.y = f2tf32(p[8 * D_MODEL]);
    o.z = f2tf32(p[4]);
    o.w = f2tf32(p[8 * D_MODEL + 4]);
    *(uint4*)&Xp[(size_t)i * 4] = o;
}

__global__ void pack_b(const float* __restrict__ W, uint32_t* __restrict__ Wp, int N)
{
    const int i    = blockIdx.x * 256 + threadIdx.x;
    const int lane = i & 31, kp = (i >> 5) & 1, slab = (i >> 6) & 31, nb = i >> 11;
    const int g = lane >> 2, t = lane & 3;
    const int n  = nb * 8 + g;
    const int k0 = slab * 32 + kp * 16 + t;
    const float* p = W + (size_t)k0 * N + n;
    uint4 o;
    o.x = f2tf32(p[0]);
    o.y = f2tf32(p[(size_t)4 * N]);
    o.z = f2tf32(p[(size_t)8 * N]);
    o.w = f2tf32(p[(size_t)12 * N]);
    *(uint4*)&Wp[(size_t)i * 4] = o;
}

// ---------------------------------------------------------------------------
// Flash packing kernels (unchanged from Round 11).
// ---------------------------------------------------------------------------
__global__ void pack_q(const float* __restrict__ Q, uint32_t* __restrict__ Qp)
{
    const float QSCALE = 0.125f * 1.44269504f;
    const int i    = blockIdx.x * 256 + threadIdx.x;
    const int lane = i & 31, c = (i >> 5) & 7, mb = (i >> 8) & 15;
    const int qt   = (i >> 12) & 7, bh = i >> 15;
    const int g = lane >> 2, t = lane & 3;
    const float* r0 = Q + ((size_t)bh * SEQ + qt * 256 + mb * 16 + g) * HD + c * 8;
    const float* r1 = r0 + 8 * HD;
    uint4 o;
    o.x = f2tf32(r0[t]     * QSCALE);
    o.y = f2tf32(r1[t]     * QSCALE);
    o.z = f2tf32(r0[t + 4] * QSCALE);
    o.w = f2tf32(r1[t + 4] * QSCALE);
    *(uint4*)&Qp[(size_t)i * 4] = o;
}

__global__ void pack_k(const float* __restrict__ K, uint32_t* __restrict__ Kp)
{
    const int i    = blockIdx.x * 256 + threadIdx.x;
    const int lane = i & 31, blk = (i >> 5) & 31, kt = (i >> 10) & 31, bh = i >> 15;
    const int g = lane >> 2, t = lane & 3;
    const int nf = blk >> 2, kp = blk & 3;
    const int key = kt * 64 + 8 * nf + g;
    const float* p = K + ((size_t)bh * SEQ + key) * HD + kp * 16 + t;
    uint4 o;
    o.x = f2tf32(p[0]);
    o.y = f2tf32(p[4]);
    o.z = f2tf32(p[8]);
    o.w = f2tf32(p[12]);
    *(uint4*)&Kp[(size_t)i * 4] = o;
}

__global__ void pack_v(const float* __restrict__ V, uint32_t* __restrict__ Vp)
{
    const int i    = blockIdx.x * 256 + threadIdx.x;
    const int lane = i & 31, blk = (i >> 5) & 31, kt = (i >> 10) & 31, bh = i >> 15;
    const int g = lane >> 2, t = lane & 3;
    const int d  = 8 * (blk >> 2) + g;
    const int key0 = kt * 64 + 16 * (blk & 3) + t;
    const float* p = V + ((size_t)bh * SEQ + key0) * HD + d;
    uint4 o;
    o.x = f2tf32(p[0]);
    o.y = f2tf32(p[(size_t)4 * HD]);
    o.z = f2tf32(p[(size_t)8 * HD]);
    o.w = f2tf32(p[(size_t)12 * HD]);
    *(uint4*)&Vp[(size_t)i * 4] = o;
}

// ---------------------------------------------------------------------------
// TF32 GEMM, cp.async 3-stage, ONE barrier per slab.
// Iteration s: wait(slab s landed) -> bar -> issue(s+2) -> compute(s).
// Buffer (s+2)%3 == (s-1)%3: its reads (compute s-1) are guarded by this
// iteration's barrier. wait_group(1) leaves only slab s+1's group pending.
// ---------------------------------------------------------------------------
#define GEMM_SMEM 98304   // 3 stages x (A 16KB + B 16KB)

template <int MODE>
__global__ void __launch_bounds__(256, 2)
gemm_mma(const uint32_t* __restrict__ Apk, const uint32_t* __restrict__ Bpk,
         const float* __restrict__ bias, float* __restrict__ Cout)
{
    constexpr int NS = 32;
    extern __shared__ uint32_t sm[];
    const int tid  = threadIdx.x;
    const int wid  = tid >> 5;
    const int lane = tid & 31;
    const int g    = lane >> 2;
    const int tig  = lane & 3;
    const int m0   = blockIdx.y * 128;
    const int n0   = blockIdx.x * 128;
    const int mb0  = m0 >> 4;
    const int nb0  = n0 >> 3;
    const uint32_t smb = smem_u32(sm);

    float acc[2][8][4];
#pragma unroll
    for (int mf = 0; mf < 2; mf++)
#pragma unroll
        for (int nf = 0; nf < 8; nf++)
#pragma unroll
            for (int r = 0; r < 4; r++) acc[mf][nf][r] = 0.0f;

    uint32_t asrc[4], bsrc[4], adst[4], bdst[4];
#pragma unroll
    for (int c = 0; c < 4; c++) {
        const int ci = c * 256 + tid;
        asrc[c] = (uint32_t)(mb0 + (ci >> 7)) * 16384u + (uint32_t)(ci & 127) * 4u;
        bsrc[c] = (uint32_t)(nb0 + (ci >> 6)) * 8192u  + (uint32_t)(ci & 63) * 4u;
        adst[c] = smb + (uint32_t)ci * 16u;
        bdst[c] = smb + 16384u + (uint32_t)ci * 16u;
    }

    auto issue = [&](int s, int buf) {
        const uint32_t so = (uint32_t)buf * 32768u;
#pragma unroll
        for (int c = 0; c < 4; c++)
            CP16(adst[c] + so, (const void*)(Apk + asrc[c] + (uint32_t)s * 512u));
#pragma unroll
        for (int c = 0; c < 4; c++)
            CP16(bdst[c] + so, (const void*)(Bpk + bsrc[c] + (uint32_t)s * 256u));
        CPCOMMIT();
    };

    issue(0, 0);
    issue(1, 1);

    const int wm4 = (wid & 3) * 2;
    const int wn8 = (wid >> 2) * 8;

    for (int s = 0; s < NS; s++) {
        if (s + 1 < NS) CPWAIT1(); else CPWAIT0();
        __syncthreads();
        if (s + 2 < NS) issue(s + 2, (s + 2) % 3);

        const uint32_t* Ab = sm + (uint32_t)(s % 3) * 8192u;
        const uint32_t* Bb = Ab + 4096;

#pragma unroll
        for (int kp = 0; kp < 2; kp++) {
            uint4 af[2][2];
#pragma unroll
            for (int mf = 0; mf < 2; mf++)
#pragma unroll
                for (int h = 0; h < 2; h++)
                    af[mf][h] = *(const uint4*)&Ab[(((wm4 + mf) * 4 + kp * 2 + h) * 32 + lane) * 4];
#pragma unroll
            for (int nf = 0; nf < 8; nf++) {
                const uint4 bv = *(const uint4*)&Bb[(((wn8 + nf) * 2 + kp) * 32 + lane) * 4];
#pragma unroll
                for (int h = 0; h < 2; h++) {
                    uint32_t b2[2];
                    b2[0] = h ? bv.z : bv.x;
                    b2[1] = h ? bv.w : bv.y;
                    mma_tf32(acc[0][nf], (const uint32_t*)&af[0][h], b2);
                    mma_tf32(acc[1][nf], (const uint32_t*)&af[1][h], b2);
                }
            }
        }
    }

#pragma unroll
    for (int mf = 0; mf < 2; mf++) {
        const int row0 = m0 + (wid & 3) * 32 + mf * 16 + g;
#pragma unroll
        for (int nf = 0; nf < 8; nf++) {
            const int col = n0 + (wid >> 2) * 64 + nf * 8 + 2 * tig;
            const float2 bv = *(const float2*)(bias + col);
            float2 v0 = make_float2(acc[mf][nf][0] + bv.x, acc[mf][nf][1] + bv.y);
            float2 v1 = make_float2(acc[mf][nf][2] + bv.x, acc[mf][nf][3] + bv.y);
            if (MODE == 0) {
                *(float2*)(Cout + (size_t)row0 * D_MODEL + col)       = v0;
                *(float2*)(Cout + (size_t)(row0 + 8) * D_MODEL + col) = v1;
            } else {
                const int which = col >> 10;
                const int c2    = col & 1023;
                const int h     = c2 >> 6;
                const int d     = c2 & 63;
                float* dst = (which == 0) ? g_Q : (which == 1) ? g_K : g_V;
                const int bb0 = row0 >> 11, t0 = row0 & 2047;
                const int r1  = row0 + 8;
                const int bb1 = r1 >> 11,   t1 = r1 & 2047;
                *(float2*)(dst + (((size_t)(bb0 * N_HEADS + h)) * SEQ + t0) * HD + d) = v0;
                *(float2*)(dst + (((size_t)(bb1 * N_HEADS + h)) * SEQ + t1) * HD + d) = v1;
            }
        }
    }
}

// ---------------------------------------------------------------------------
// Flash attention (Round-12): pre-packed operands, 3-stage KV cp.async
// pipeline, ONE barrier per key tile (same reorg as the GEMM).
// Smem: Q 64KB + 3 x (K 16KB + V 16KB) = 160KB.
// ---------------------------------------------------------------------------
#define QROWS 256
#define QP_U32 (QROWS * HD)              // 16384 u32 = 64KB
#define KVT_U32 4096                     // one K or V tile = 16KB
#define FLASH_SMEM ((QP_U32 + 3 * 2 * KVT_U32) * 4)   // 163840

__global__ void __launch_bounds__(256, 1)
flash_mma()
{
    extern __shared__ uint32_t fsm[];
    uint4* Qp4 = (uint4*)fsm;            // packed A-frag
    const uint32_t smb = smem_u32(fsm);

    const int tid  = threadIdx.x;
    const int wid  = tid >> 5;
    const int lane = tid & 31;
    const int g    = lane >> 2;
    const int tig  = lane & 3;
    const int qt   = (int)gridDim.x - 1 - (int)blockIdx.x;
    const int bh   = blockIdx.y;
    const int q0   = qt * QROWS;
    const int nt   = qt * 4 + 4;

    const uint32_t* qg = g_Qp + ((size_t)bh * 8 + qt) * QP_U32;
    const uint32_t* kg = g_Kp + (size_t)bh * 32 * KVT_U32;
    const uint32_t* vg = g_Vp + (size_t)bh * 32 * KVT_U32;

    // Q copy: 16 x CP16 per thread, one group (retires before first KV wait).
#pragma unroll
    for (int c = 0; c < 16; c++)
        CP16(smb + (uint32_t)(c * 256 + tid) * 16u,
             (const void*)(qg + (size_t)(c * 256 + tid) * 4));
    CPCOMMIT();

    auto issueKV = [&](int kt, int buf) {
        const uint32_t so = smb + (uint32_t)(QP_U32 + buf * 2 * KVT_U32) * 4u;
        const uint32_t* ks = kg + (size_t)kt * KVT_U32;
        const uint32_t* vs = vg + (size_t)kt * KVT_U32;
#pragma unroll
        for (int c = 0; c < 4; c++)
            CP16(so + (uint32_t)(c * 256 + tid) * 16u,
                 (const void*)(ks + (size_t)(c * 256 + tid) * 4));
#pragma unroll
        for (int c = 0; c < 4; c++)
            CP16(so + (uint32_t)KVT_U32 * 4u + (uint32_t)(c * 256 + tid) * 16u,
                 (const void*)(vs + (size_t)(c * 256 + tid) * 4));
        CPCOMMIT();
    };

    issueKV(0, 0);
    issueKV(1, 1);    // nt >= 4 always

    float mrow[2][2], lrow[2][2], Of[2][8][4];
#pragma unroll
    for (int mf = 0; mf < 2; mf++) {
        mrow[mf][0] = mrow[mf][1] = -1e30f;
        lrow[mf][0] = lrow[mf][1] = 0.0f;
#pragma unroll
        for (int nf = 0; nf < 8; nf++)
#pragma unroll
            for (int r = 0; r < 4; r++) Of[mf][nf][r] = 0.0f;
    }

    for (int kt = 0; kt < nt; kt++) {
        if (kt + 1 < nt) CPWAIT1(); else CPWAIT0();
        __syncthreads();
        if (kt + 2 < nt) issueKV(kt + 2, (kt + 2) % 3);

        const uint32_t* Kps = fsm + QP_U32 + (kt % 3) * 2 * KVT_U32;
        const uint32_t* Vps = Kps + KVT_U32;

        // ---- S = Q K^T ----
        float sacc[2][8][4];
#pragma unroll
        for (int mf = 0; mf < 2; mf++)
#pragma unroll
            for (int nf = 0; nf < 8; nf++)
#pragma unroll
                for (int r = 0; r < 4; r++) sacc[mf][nf][r] = 0.0f;

#pragma unroll
        for (int kp = 0; kp < 4; kp++) {
            uint4 aq[2][2];
#pragma unroll
            for (int mf = 0; mf < 2; mf++)
#pragma unroll
                for (int h = 0; h < 2; h++)
                    aq[mf][h] = Qp4[((wid * 2 + mf) * 8 + kp * 2 + h) * 32 + lane];
#pragma unroll
            for (int half = 0; half < 2; half++) {
                uint4 kb[4];
#pragma unroll
                for (int i = 0; i < 4; i++)
                    kb[i] = *(const uint4*)&Kps[(((half * 4 + i) * 4 + kp) * 32 + lane) * 4];
#pragma unroll
                for (int h = 0; h < 2; h++)
#pragma unroll
                    for (int i = 0; i < 4; i++) {
                        uint32_t b[2];
                        b[0] = h ? kb[i].z : kb[i].x;
                        b[1] = h ? kb[i].w : kb[i].y;
                        mma_tf32(sacc[0][half * 4 + i], (const uint32_t*)&aq[0][h], b);
                        mma_tf32(sacc[1][half * 4 + i], (const uint32_t*)&aq[1][h], b);
                    }
            }
        }

        // Causal mask
        if (kt >= nt - 4) {
            const int n0 = kt * 64;
#pragma unroll
            for (int mf = 0; mf < 2; mf++) {
                const int r0g = q0 + wid * 32 + mf * 16 + g;
#pragma unroll
                for (int nf = 0; nf < 8; nf++) {
                    const int c0 = n0 + nf * 8 + 2 * tig;
                    if (c0     > r0g)     sacc[mf][nf][0] = -1e30f;
                    if (c0 + 1 > r0g)     sacc[mf][nf][1] = -1e30f;
                    if (c0     > r0g + 8) sacc[mf][nf][2] = -1e30f;
                    if (c0 + 1 > r0g + 8) sacc[mf][nf][3] = -1e30f;
                }
            }
        }

        // ---- Online softmax ----
        uint32_t P0[2][8], P1[2][8], P2[2][8], P3[2][8];
#pragma unroll
        for (int mf = 0; mf < 2; mf++) {
            float rm0 = -1e30f, rm1 = -1e30f;
#pragma unroll
            for (int nf = 0; nf < 8; nf++) {
                rm0 = fmaxf(rm0, fmaxf(sacc[mf][nf][0], sacc[mf][nf][1]));
                rm1 = fmaxf(rm1, fmaxf(sacc[mf][nf][2], sacc[mf][nf][3]));
            }
            rm0 = fmaxf(rm0, __shfl_xor_sync(0xffffffffu, rm0, 1));
            rm0 = fmaxf(rm0, __shfl_xor_sync(0xffffffffu, rm0, 2));
            rm1 = fmaxf(rm1, __shfl_xor_sync(0xffffffffu, rm1, 1));
            rm1 = fmaxf(rm1, __shfl_xor_sync(0xffffffffu, rm1, 2));

            const float nm0 = fmaxf(mrow[mf][0], rm0);
            const float nm1 = fmaxf(mrow[mf][1], rm1);
            const float al0 = exp2f(mrow[mf][0] - nm0);
            const float al1 = exp2f(mrow[mf][1] - nm1);
            mrow[mf][0] = nm0; mrow[mf][1] = nm1;

            float rs0 = 0.0f, rs1 = 0.0f;
#pragma unroll
            for (int nf = 0; nf < 8; nf++) {
                const float p0 = exp2f(sacc[mf][nf][0] - nm0);
                const float p1 = exp2f(sacc[mf][nf][1] - nm0);
                const float p2 = exp2f(sacc[mf][nf][2] - nm1);
                const float p3 = exp2f(sacc[mf][nf][3] - nm1);
                rs0 += p0 + p1;
                rs1 += p2 + p3;
                P0[mf][nf] = f2tf32(p0); P1[mf][nf] = f2tf32(p1);
                P2[mf][nf] = f2tf32(p2); P3[mf][nf] = f2tf32(p3);
            }
            rs0 += __shfl_xor_sync(0xffffffffu, rs0, 1);
            rs0 += __shfl_xor_sync(0xffffffffu, rs0, 2);
            rs1 += __shfl_xor_sync(0xffffffffu, rs1, 1);
            rs1 += __shfl_xor_sync(0xffffffffu, rs1, 2);
            lrow[mf][0] = lrow[mf][0] * al0 + rs0;
            lrow[mf][1] = lrow[mf][1] * al1 + rs1;

#pragma unroll
            for (int nf = 0; nf < 8; nf++) {
                Of[mf][nf][0] *= al0; Of[mf][nf][1] *= al0;
                Of[mf][nf][2] *= al1; Of[mf][nf][3] *= al1;
            }
        }

        // ---- O += P V ----
        const int srcA = (lane & 28) | (tig >> 1);
        const int srcB = srcA + 2;
        const bool hi  = (tig & 1);
#pragma unroll
        for (int kp = 0; kp < 4; kp++) {
            uint32_t ap[2][2][4];
#pragma unroll
            for (int mf = 0; mf < 2; mf++)
#pragma unroll
                for (int h = 0; h < 2; h++) {
                    const int kc = kp * 2 + h;
                    uint32_t x0 = __shfl_sync(0xffffffffu, P0[mf][kc], srcA);
                    uint32_t x1 = __shfl_sync(0xffffffffu, P1[mf][kc], srcA);
                    uint32_t y0 = __shfl_sync(0xffffffffu, P2[mf][kc], srcA);
                    uint32_t y1 = __shfl_sync(0xffffffffu, P3[mf][kc], srcA);
                    uint32_t z0 = __shfl_sync(0xffffffffu, P0[mf][kc], srcB);
                    uint32_t z1 = __shfl_sync(0xffffffffu, P1[mf][kc], srcB);
                    uint32_t w0 = __shfl_sync(0xffffffffu, P2[mf][kc], srcB);
                    uint32_t w1 = __shfl_sync(0xffffffffu, P3[mf][kc], srcB);
                    ap[mf][h][0] = hi ? x1 : x0;
                    ap[mf][h][1] = hi ? y1 : y0;
                    ap[mf][h][2] = hi ? z1 : z0;
                    ap[mf][h][3] = hi ? w1 : w0;
                }
#pragma unroll
            for (int half = 0; half < 2; half++) {
                uint4 vb[4];
#pragma unroll
                for (int i = 0; i < 4; i++)
                    vb[i] = *(const uint4*)&Vps[(((half * 4 + i) * 4 + kp) * 32 + lane) * 4];
#pragma unroll
                for (int h = 0; h < 2; h++)
#pragma unroll
                    for (int i = 0; i < 4; i++) {
                        uint32_t b[2];
                        b[0] = h ? vb[i].z : vb[i].x;
                        b[1] = h ? vb[i].w : vb[i].y;
                        mma_tf32(Of[0][half * 4 + i], ap[0][h], b);
                        mma_tf32(Of[1][half * 4 + i], ap[1][h], b);
                    }
            }
        }
    }

    // Epilogue: write packed tf32 A-fragment g_Yp (quad-shuffle transform).
    const int b = bh >> 4;
    const int h = bh & 15;
    const int srcA = (lane & 28) | (tig >> 1);
    const int srcB = srcA + 2;
    const bool hi  = (tig & 1);
#pragma unroll
    for (int mf = 0; mf < 2; mf++) {
        const float inv0 = 1.0f / lrow[mf][0];
        const float inv1 = 1.0f / lrow[mf][1];
        const int mb = (b * SEQ + q0 + wid * 32 + mf * 16) >> 4;
#pragma unroll
        for (int j = 0; j < 8; j++) {
            const float n0f = Of[mf][j][0] * inv0;
            const float n1f = Of[mf][j][1] * inv0;
            const float n2f = Of[mf][j][2] * inv1;
            const float n3f = Of[mf][j][3] * inv1;
            const float x0 = __shfl_sync(0xffffffffu, n0f, srcA);
            const float x1 = __shfl_sync(0xffffffffu, n1f, srcA);
            const float y0 = __shfl_sync(0xffffffffu, n2f, srcA);
            const float y1 = __shfl_sync(0xffffffffu, n3f, srcA);
            const float z0 = __shfl_sync(0xffffffffu, n0f, srcB);
            const float z1 = __shfl_sync(0xffffffffu, n1f, srcB);
            const float w0 = __shfl_sync(0xffffffffu, n2f, srcB);
            const float w1 = __shfl_sync(0xffffffffu, n3f, srcB);
            uint4 o;
            o.x = f2tf32(hi ? x1 : x0);
            o.y = f2tf32(hi ? y1 : y0);
            o.z = f2tf32(hi ? z1 : z0);
            o.w = f2tf32(hi ? w1 : w0);
            const int slab = 2 * h + (j >> 2);
            const int kc   = j & 3;
            *(uint4*)&g_Yp[(((size_t)mb * 32 + slab) * 4 + kc) * 128 + lane * 4] = o;
        }
    }
}

// ---------------------------------------------------------------------------
extern "C" void kernel_launch(void* const* d_in, const int* in_sizes, int n_in,
                              void* d_out, int out_size)
{
    const float* x      = (const float*)d_in[0];
    const float* W_attn = (const float*)d_in[1];
    const float* b_attn = (const float*)d_in[2];
    const float* W_proj = (const float*)d_in[3];
    const float* b_proj = (const float*)d_in[4];
    float* out = (float*)d_out;

    cudaFuncSetAttribute(gemm_mma<1>, cudaFuncAttributeMaxDynamicSharedMemorySize, GEMM_SMEM);
    cudaFuncSetAttribute(gemm_mma<0>, cudaFuncAttributeMaxDynamicSharedMemorySize, GEMM_SMEM);
    cudaFuncSetAttribute(flash_mma, cudaFuncAttributeMaxDynamicSharedMemorySize, FLASH_SMEM);

    float*    q;   cudaGetSymbolAddress((void**)&q,   g_Q);
    float*    k;   cudaGetSymbolAddress((void**)&k,   g_K);
    float*    v;   cudaGetSymbolAddress((void**)&v,   g_V);
    uint32_t* xp;  cudaGetSymbolAddress((void**)&xp,  g_Xp);
    uint32_t* yp;  cudaGetSymbolAddress((void**)&yp,  g_Yp);
    uint32_t* wpa; cudaGetSymbolAddress((void**)&wpa, g_Wpa);
    uint32_t* wpp; cudaGetSymbolAddress((void**)&wpp, g_Wpp);
    uint32_t* qp;  cudaGetSymbolAddress((void**)&qp,  g_Qp);
    uint32_t* kp;  cudaGetSymbolAddress((void**)&kp,  g_Kp);
    uint32_t* vp;  cudaGetSymbolAddress((void**)&vp,  g_Vp);

    const int QKV_U4 = (BH * SEQ * HD / 4) / 256;   // 8192 blocks

    // 0) Pack GEMM operands
    pack_a<<<(M_TOK * D_MODEL / 4) / 256, 256>>>(x, xp);
    pack_b<<<(3 * D_MODEL * D_MODEL / 4) / 256, 256>>>(W_attn, wpa, 3 * D_MODEL);
    pack_b<<<(D_MODEL * D_MODEL / 4) / 256, 256>>>(W_proj, wpp, D_MODEL);

    // 1) QKV projection -> g_Q/g_K/g_V (fp32, head-major)
    {
        dim3 grid(3 * D_MODEL / 128, M_TOK / 128);  // (24, 64)
        gemm_mma<1><<<grid, 256, GEMM_SMEM>>>(xp, wpa, b_attn, nullptr);
    }
    // 1.5) Pack Q/K/V into fragment-layout tf32
    pack_q<<<QKV_U4, 256>>>(q, qp);
    pack_k<<<QKV_U4, 256>>>(k, kp);
    pack_v<<<QKV_U4, 256>>>(v, vp);

    // 2) Causal flash attention -> g_Yp (packed tf32)
    {
        dim3 grid(SEQ / QROWS, BH);  // (8, 64)
        flash_mma<<<grid, 256, FLASH_SMEM>>>();
    }
    // 3) Output projection -> d_out
    {
        dim3 grid(D_MODEL / 128, M_TOK / 128);  // (8, 64)
        gemm_mma<0><<<grid, 256, GEMM_SMEM>>>(yp, wpp, b_proj, out);
    }
}

// round 13
// speedup vs baseline: 1.0963x; 1.0963x over previous
#include <cuda_runtime.h>
#include <math.h>
#include <stdint.h>

// Problem constants
#define D_MODEL 1024
#define N_HEADS 16
#define HD      64
#define BATCH   4
#define SEQ     2048
#define BH      (BATCH * N_HEADS)   // 64
#define M_TOK   (BATCH * SEQ)       // 8192

// Scratch (device globals: allocation-free per harness rules)
__device__ uint32_t g_Xp[(size_t)M_TOK * D_MODEL];        // x, packed tf32 A-frag
__device__ uint32_t g_Yp[(size_t)M_TOK * D_MODEL];        // attn out, packed tf32 A-frag
__device__ uint32_t g_Wpa[(size_t)3 * D_MODEL * D_MODEL]; // W_attn^T packed tf32 B-frag
__device__ uint32_t g_Wpp[(size_t)D_MODEL * D_MODEL];     // W_proj^T packed tf32 B-frag
__device__ uint32_t g_Qp[(size_t)BH * SEQ * HD];          // Q packed tf32 A-frag (scaled)
__device__ uint32_t g_Kp[(size_t)BH * SEQ * HD];          // K packed tf32 B-frag
__device__ uint32_t g_Vp[(size_t)BH * SEQ * HD];          // V packed tf32 B-frag (n=d)

// ---------------------------------------------------------------------------
// Helpers (base-target ISA; sm_80+)
// ---------------------------------------------------------------------------
__device__ __forceinline__ uint32_t f2tf32(float f) {
    uint32_t r;
    asm("cvt.rna.tf32.f32 %0, %1;" : "=r"(r) : "f"(f));
    return r;
}
__device__ __forceinline__ void mma_tf32(float d[4], const uint32_t a[4],
                                         const uint32_t b[2]) {
    asm volatile(
        "mma.sync.aligned.m16n8k8.row.col.f32.tf32.tf32.f32 "
        "{%0,%1,%2,%3}, {%4,%5,%6,%7}, {%8,%9}, {%0,%1,%2,%3};"
        : "+f"(d[0]), "+f"(d[1]), "+f"(d[2]), "+f"(d[3])
        : "r"(a[0]), "r"(a[1]), "r"(a[2]), "r"(a[3]), "r"(b[0]), "r"(b[1]));
}
__device__ __forceinline__ uint32_t smem_u32(const void* p) {
    uint32_t a;
    asm("{ .reg .u64 t; cvta.to.shared.u64 t, %1; cvt.u32.u64 %0, t; }"
        : "=r"(a) : "l"(p));
    return a;
}
#define CP16(dst, src) \
    asm volatile("cp.async.cg.shared.global [%0], [%1], 16;" \
                 :: "r"(dst), "l"(src) : "memory")
#define CPCOMMIT() asm volatile("cp.async.commit_group;" ::: "memory")
#define CPWAIT1()  asm volatile("cp.async.wait_group 1;" ::: "memory")
#define CPWAIT0()  asm volatile("cp.async.wait_group 0;" ::: "memory")

// ---------------------------------------------------------------------------
// GEMM packing kernels (unchanged).
// ---------------------------------------------------------------------------
__global__ void pack_a(const float* __restrict__ X, uint32_t* __restrict__ Xp)
{
    const int i    = blockIdx.x * 256 + threadIdx.x;   // uint4 index
    const int lane = i & 31, kc = (i >> 5) & 3, slab = (i >> 7) & 31, mb = i >> 12;
    const int g = lane >> 2, t = lane & 3;
    const float* p = X + ((size_t)(mb * 16 + g)) * D_MODEL + slab * 32 + kc * 8 + t;
    uint4 o;
    o.x = f2tf32(p[0]);
    o.y = f2tf32(p[8 * D_MODEL]);
    o.z = f2tf32(p[4]);
    o.w = f2tf32(p[8 * D_MODEL + 4]);
    *(uint4*)&Xp[(size_t)i * 4] = o;
}

__global__ void pack_b(const float* __restrict__ W, uint32_t* __restrict__ Wp, int N)
{
    const int i    = blockIdx.x * 256 + threadIdx.x;
    const int lane = i & 31, kp = (i >> 5) & 1, slab = (i >> 6) & 31, nb = i >> 11;
    const int g = lane >> 2, t = lane & 3;
    const int n  = nb * 8 + g;
    const int k0 = slab * 32 + kp * 16 + t;
    const float* p = W + (size_t)k0 * N + n;
    uint4 o;
    o.x = f2tf32(p[0]);
    o.y = f2tf32(p[(size_t)4 * N]);
    o.z = f2tf32(p[(size_t)8 * N]);
    o.w = f2tf32(p[(size_t)12 * N]);
    *(uint4*)&Wp[(size_t)i * 4] = o;
}

// ---------------------------------------------------------------------------
// TF32 GEMM, cp.async 2-stage (Round-11 structure, proven).
// MODE 1: epilogue writes g_Qp/g_Kp/g_Vp DIRECTLY in fragment layout (fused
//   packing via warp shuffles; same fp32 values through same cvt points).
// MODE 0: epilogue writes Cout + bias (fp32).
// ---------------------------------------------------------------------------
#define GEMM_SMEM 65536

template <int MODE>
__global__ void __launch_bounds__(256, 2)
gemm_mma(const uint32_t* __restrict__ Apk, const uint32_t* __restrict__ Bpk,
         const float* __restrict__ bias, float* __restrict__ Cout)
{
    constexpr int NS = 32;
    extern __shared__ uint32_t sm[];
    const int tid  = threadIdx.x;
    const int wid  = tid >> 5;
    const int lane = tid & 31;
    const int g    = lane >> 2;
    const int tig  = lane & 3;
    const int m0   = blockIdx.y * 128;
    const int n0   = blockIdx.x * 128;
    const int mb0  = m0 >> 4;
    const int nb0  = n0 >> 3;
    const uint32_t smb = smem_u32(sm);

    float acc[2][8][4];
#pragma unroll
    for (int mf = 0; mf < 2; mf++)
#pragma unroll
        for (int nf = 0; nf < 8; nf++)
#pragma unroll
            for (int r = 0; r < 4; r++) acc[mf][nf][r] = 0.0f;

    uint32_t asrc[4], bsrc[4], adst[4], bdst[4];
#pragma unroll
    for (int c = 0; c < 4; c++) {
        const int ci = c * 256 + tid;
        asrc[c] = (uint32_t)(mb0 + (ci >> 7)) * 16384u + (uint32_t)(ci & 127) * 4u;
        bsrc[c] = (uint32_t)(nb0 + (ci >> 6)) * 8192u  + (uint32_t)(ci & 63) * 4u;
        adst[c] = smb + (uint32_t)ci * 16u;
        bdst[c] = smb + 16384u + (uint32_t)ci * 16u;
    }

    auto issue = [&](int s, int buf) {
        const uint32_t so = (uint32_t)buf * 32768u;
#pragma unroll
        for (int c = 0; c < 4; c++)
            CP16(adst[c] + so, (const void*)(Apk + asrc[c] + (uint32_t)s * 512u));
#pragma unroll
        for (int c = 0; c < 4; c++)
            CP16(bdst[c] + so, (const void*)(Bpk + bsrc[c] + (uint32_t)s * 256u));
        CPCOMMIT();
    };

    issue(0, 0);

    const int wm4 = (wid & 3) * 2;
    const int wn8 = (wid >> 2) * 8;

    for (int s = 0; s < NS; s++) {
        if (s + 1 < NS) { issue(s + 1, (s + 1) & 1); CPWAIT1(); }
        else            { CPWAIT0(); }
        __syncthreads();

        const uint32_t* Ab = sm + (uint32_t)(s & 1) * 8192u;
        const uint32_t* Bb = Ab + 4096;

#pragma unroll
        for (int kp = 0; kp < 2; kp++) {
            uint4 af[2][2];
#pragma unroll
            for (int mf = 0; mf < 2; mf++)
#pragma unroll
                for (int h = 0; h < 2; h++)
                    af[mf][h] = *(const uint4*)&Ab[(((wm4 + mf) * 4 + kp * 2 + h) * 32 + lane) * 4];
#pragma unroll
            for (int nf = 0; nf < 8; nf++) {
                const uint4 bv = *(const uint4*)&Bb[(((wn8 + nf) * 2 + kp) * 32 + lane) * 4];
#pragma unroll
                for (int h = 0; h < 2; h++) {
                    uint32_t b2[2];
                    b2[0] = h ? bv.z : bv.x;
                    b2[1] = h ? bv.w : bv.y;
                    mma_tf32(acc[0][nf], (const uint32_t*)&af[0][h], b2);
                    mma_tf32(acc[1][nf], (const uint32_t*)&af[1][h], b2);
                }
            }
        }
        __syncthreads();
    }

    if (MODE == 0) {
#pragma unroll
        for (int mf = 0; mf < 2; mf++) {
            const int row0 = m0 + (wid & 3) * 32 + mf * 16 + g;
#pragma unroll
            for (int nf = 0; nf < 8; nf++) {
                const int col = n0 + (wid >> 2) * 64 + nf * 8 + 2 * tig;
                const float2 bv = *(const float2*)(bias + col);
                *(float2*)(Cout + (size_t)row0 * D_MODEL + col) =
                    make_float2(acc[mf][nf][0] + bv.x, acc[mf][nf][1] + bv.y);
                *(float2*)(Cout + (size_t)(row0 + 8) * D_MODEL + col) =
                    make_float2(acc[mf][nf][2] + bv.x, acc[mf][nf][3] + bv.y);
            }
        }
    } else {
        // Fused pack: write Q/K/V directly in fragment layout.
        const float QSCALE = 0.125f * 1.44269504f;
        const int colbase = n0 + (wid >> 2) * 64;   // 64-aligned -> one head
        const int which = colbase >> 10;            // 0=Q 1=K 2=V
        const int h     = (colbase & 1023) >> 6;
        const int srcA  = (lane & 28) | (tig >> 1);
        const int srcB  = srcA + 2;
        const bool hi   = (tig & 1);

#pragma unroll
        for (int mf = 0; mf < 2; mf++) {
            const int mbase = m0 + (wid & 3) * 32 + mf * 16;   // 16-aligned token
            const int b  = mbase >> 11;
            const int tb = mbase & 2047;
            const int bh = b * N_HEADS + h;
            const int kt = tb >> 6;

            // Biased fp32 values (same numbers as the old fp32 store + pack)
            float v0[8], v1[8], v2[8], v3[8];
#pragma unroll
            for (int nf = 0; nf < 8; nf++) {
                const int col = colbase + nf * 8 + 2 * tig;
                const float2 bv = *(const float2*)(bias + col);
                v0[nf] = acc[mf][nf][0] + bv.x;
                v1[nf] = acc[mf][nf][1] + bv.y;
                v2[nf] = acc[mf][nf][2] + bv.x;
                v3[nf] = acc[mf][nf][3] + bv.y;
            }

            if (which == 0) {
                // A-frag (pack_q layout), QSCALE folded in.
                const int qt = tb >> 8, mb = (tb >> 4) & 15;
                uint32_t* base = g_Qp
                    + (size_t)((bh * 8 + qt) * 16 + mb) * 1024 + lane * 4;
#pragma unroll
                for (int c = 0; c < 8; c++) {
                    const float a0 = v0[c] * QSCALE, a1 = v1[c] * QSCALE;
                    const float a2 = v2[c] * QSCALE, a3 = v3[c] * QSCALE;
                    const float x0 = __shfl_sync(0xffffffffu, a0, srcA);
                    const float x1 = __shfl_sync(0xffffffffu, a1, srcA);
                    const float y0 = __shfl_sync(0xffffffffu, a2, srcA);
                    const float y1 = __shfl_sync(0xffffffffu, a3, srcA);
                    const float z0 = __shfl_sync(0xffffffffu, a0, srcB);
                    const float z1 = __shfl_sync(0xffffffffu, a1, srcB);
                    const float w0 = __shfl_sync(0xffffffffu, a2, srcB);
                    const float w1 = __shfl_sync(0xffffffffu, a3, srcB);
                    uint4 o;
                    o.x = f2tf32(hi ? x1 : x0);
                    o.y = f2tf32(hi ? y1 : y0);
                    o.z = f2tf32(hi ? z1 : z0);
                    o.w = f2tf32(hi ? w1 : w0);
                    *(uint4*)(base + (size_t)c * 128) = o;
                }
            } else if (which == 1) {
                // B-frag (pack_k layout): target (g,t) = key 8*nfk+g,
                // d = 16kp + t (+4, +8, +12).
                const int nfk0 = (tb >> 3) & 7;
                uint32_t* base = g_Kp + (size_t)(kt + 32 * bh) * 4096 + lane * 4;
#pragma unroll
                for (int rb = 0; rb < 2; rb++) {
#pragma unroll
                    for (int kp = 0; kp < 4; kp++) {
                        const float a  = rb ? v2[2 * kp]     : v0[2 * kp];
                        const float bb = rb ? v3[2 * kp]     : v1[2 * kp];
                        const float cc = rb ? v2[2 * kp + 1] : v0[2 * kp + 1];
                        const float dd = rb ? v3[2 * kp + 1] : v1[2 * kp + 1];
                        const float xa = __shfl_sync(0xffffffffu, a,  srcA);
                        const float xb = __shfl_sync(0xffffffffu, bb, srcA);
                        const float ya = __shfl_sync(0xffffffffu, a,  srcB);
                        const float yb = __shfl_sync(0xffffffffu, bb, srcB);
                        const float za = __shfl_sync(0xffffffffu, cc, srcA);
                        const float zb = __shfl_sync(0xffffffffu, dd, srcA);
                        const float wa = __shfl_sync(0xffffffffu, cc, srcB);
                        const float wb = __shfl_sync(0xffffffffu, dd, srcB);
                        uint4 o;
                        o.x = f2tf32(hi ? xb : xa);
                        o.y = f2tf32(hi ? yb : ya);
                        o.z = f2tf32(hi ? zb : za);
                        o.w = f2tf32(hi ? wb : wa);
                        const int blk = 4 * (nfk0 + rb) + kp;
                        *(uint4*)(base + (size_t)blk * 128) = o;
                    }
                }
            } else {
                // B-frag transposed (pack_v layout): target (g,t) = d 8*nfv+g,
                // keys 16kpv + t (+4, +8, +12). Cross-quad shuffle.
                const int kpv = (tb >> 4) & 3;
                const int L0 = tig * 4 + (g >> 1);
                const int L1 = (tig + 4) * 4 + (g >> 1);
                const bool gp = (g & 1);
                uint32_t* base = g_Vp + (size_t)(kt + 32 * bh) * 4096 + lane * 4;
#pragma unroll
                for (int nfv = 0; nfv < 8; nfv++) {
                    const float x0 = __shfl_sync(0xffffffffu, v0[nfv], L0);
                    const float x1 = __shfl_sync(0xffffffffu, v1[nfv], L0);
                    const float y0 = __shfl_sync(0xffffffffu, v0[nfv], L1);
                    const float y1 = __shfl_sync(0xffffffffu, v1[nfv], L1);
                    const float z0 = __shfl_sync(0xffffffffu, v2[nfv], L0);
                    const float z1 = __shfl_sync(0xffffffffu, v3[nfv], L0);
                    const float w0 = __shfl_sync(0xffffffffu, v2[nfv], L1);
                    const float w1 = __shfl_sync(0xffffffffu, v3[nfv], L1);
                    uint4 o;
                    o.x = f2tf32(gp ? x1 : x0);
                    o.y = f2tf32(gp ? y1 : y0);
                    o.z = f2tf32(gp ? z1 : z0);
                    o.w = f2tf32(gp ? w1 : w0);
                    const int blk = 4 * nfv + kpv;
                    *(uint4*)(base + (size_t)blk * 128) = o;
                }
            }
        }
    }
}

// ---------------------------------------------------------------------------
// Flash attention (Round-11 structure, proven): pre-packed operands,
// Q staged once, 2-stage KV cp.async pipeline.
// ---------------------------------------------------------------------------
#define QROWS 256
#define QP_U32 (QROWS * HD)              // 16384 u32 = 64KB
#define KVT_U32 4096                     // one K or V tile = 16KB
#define FLASH_SMEM ((QP_U32 + 2 * 2 * KVT_U32) * 4)   // 131072

__global__ void __launch_bounds__(256, 1)
flash_mma()
{
    extern __shared__ uint32_t fsm[];
    uint4* Qp4 = (uint4*)fsm;            // packed A-frag
    const uint32_t smb = smem_u32(fsm);

    const int tid  = threadIdx.x;
    const int wid  = tid >> 5;
    const int lane = tid & 31;
    const int g    = lane >> 2;
    const int tig  = lane & 3;
    const int qt   = (int)gridDim.x - 1 - (int)blockIdx.x;
    const int bh   = blockIdx.y;
    const int q0   = qt * QROWS;
    const int nt   = qt * 4 + 4;

    const uint32_t* qg = g_Qp + ((size_t)bh * 8 + qt) * QP_U32;
    const uint32_t* kg = g_Kp + (size_t)bh * 32 * KVT_U32;
    const uint32_t* vg = g_Vp + (size_t)bh * 32 * KVT_U32;

#pragma unroll
    for (int c = 0; c < 16; c++)
        CP16(smb + (uint32_t)(c * 256 + tid) * 16u,
             (const void*)(qg + (size_t)(c * 256 + tid) * 4));
    CPCOMMIT();

    auto issueKV = [&](int kt, int buf) {
        const uint32_t so = smb + (uint32_t)(QP_U32 + buf * 2 * KVT_U32) * 4u;
        const uint32_t* ks = kg + (size_t)kt * KVT_U32;
        const uint32_t* vs = vg + (size_t)kt * KVT_U32;
#pragma unroll
        for (int c = 0; c < 4; c++)
            CP16(so + (uint32_t)(c * 256 + tid) * 16u,
                 (const void*)(ks + (size_t)(c * 256 + tid) * 4));
#pragma unroll
        for (int c = 0; c < 4; c++)
            CP16(so + (uint32_t)KVT_U32 * 4u + (uint32_t)(c * 256 + tid) * 16u,
                 (const void*)(vs + (size_t)(c * 256 + tid) * 4));
        CPCOMMIT();
    };

    issueKV(0, 0);

    float mrow[2][2], lrow[2][2], Of[2][8][4];
#pragma unroll
    for (int mf = 0; mf < 2; mf++) {
        mrow[mf][0] = mrow[mf][1] = -1e30f;
        lrow[mf][0] = lrow[mf][1] = 0.0f;
#pragma unroll
        for (int nf = 0; nf < 8; nf++)
#pragma unroll
            for (int r = 0; r < 4; r++) Of[mf][nf][r] = 0.0f;
    }

    for (int kt = 0; kt < nt; kt++) {
        if (kt + 1 < nt) { issueKV(kt + 1, (kt + 1) & 1); CPWAIT1(); }
        else             { CPWAIT0(); }
        __syncthreads();

        const uint32_t* Kps = fsm + QP_U32 + (kt & 1) * 2 * KVT_U32;
        const uint32_t* Vps = Kps + KVT_U32;

        // ---- S = Q K^T ----
        float sacc[2][8][4];
#pragma unroll
        for (int mf = 0; mf < 2; mf++)
#pragma unroll
            for (int nf = 0; nf < 8; nf++)
#pragma unroll
                for (int r = 0; r < 4; r++) sacc[mf][nf][r] = 0.0f;

#pragma unroll
        for (int kp = 0; kp < 4; kp++) {
            uint4 aq[2][2];
#pragma unroll
            for (int mf = 0; mf < 2; mf++)
#pragma unroll
                for (int h = 0; h < 2; h++)
                    aq[mf][h] = Qp4[((wid * 2 + mf) * 8 + kp * 2 + h) * 32 + lane];
#pragma unroll
            for (int half = 0; half < 2; half++) {
                uint4 kb[4];
#pragma unroll
                for (int i = 0; i < 4; i++)
                    kb[i] = *(const uint4*)&Kps[(((half * 4 + i) * 4 + kp) * 32 + lane) * 4];
#pragma unroll
                for (int h = 0; h < 2; h++)
#pragma unroll
                    for (int i = 0; i < 4; i++) {
                        uint32_t b[2];
                        b[0] = h ? kb[i].z : kb[i].x;
                        b[1] = h ? kb[i].w : kb[i].y;
                        mma_tf32(sacc[0][half * 4 + i], (const uint32_t*)&aq[0][h], b);
                        mma_tf32(sacc[1][half * 4 + i], (const uint32_t*)&aq[1][h], b);
                    }
            }
        }

        // Causal mask
        if (kt >= nt - 4) {
            const int n0 = kt * 64;
#pragma unroll
            for (int mf = 0; mf < 2; mf++) {
                const int r0g = q0 + wid * 32 + mf * 16 + g;
#pragma unroll
                for (int nf = 0; nf < 8; nf++) {
                    const int c0 = n0 + nf * 8 + 2 * tig;
                    if (c0     > r0g)     sacc[mf][nf][0] = -1e30f;
                    if (c0 + 1 > r0g)     sacc[mf][nf][1] = -1e30f;
                    if (c0     > r0g + 8) sacc[mf][nf][2] = -1e30f;
                    if (c0 + 1 > r0g + 8) sacc[mf][nf][3] = -1e30f;
                }
            }
        }

        // ---- Online softmax ----
        uint32_t P0[2][8], P1[2][8], P2[2][8], P3[2][8];
#pragma unroll
        for (int mf = 0; mf < 2; mf++) {
            float rm0 = -1e30f, rm1 = -1e30f;
#pragma unroll
            for (int nf = 0; nf < 8; nf++) {
                rm0 = fmaxf(rm0, fmaxf(sacc[mf][nf][0], sacc[mf][nf][1]));
                rm1 = fmaxf(rm1, fmaxf(sacc[mf][nf][2], sacc[mf][nf][3]));
            }
            rm0 = fmaxf(rm0, __shfl_xor_sync(0xffffffffu, rm0, 1));
            rm0 = fmaxf(rm0, __shfl_xor_sync(0xffffffffu, rm0, 2));
            rm1 = fmaxf(rm1, __shfl_xor_sync(0xffffffffu, rm1, 1));
            rm1 = fmaxf(rm1, __shfl_xor_sync(0xffffffffu, rm1, 2));

            const float nm0 = fmaxf(mrow[mf][0], rm0);
            const float nm1 = fmaxf(mrow[mf][1], rm1);
            const float al0 = exp2f(mrow[mf][0] - nm0);
            const float al1 = exp2f(mrow[mf][1] - nm1);
            mrow[mf][0] = nm0; mrow[mf][1] = nm1;

            float rs0 = 0.0f, rs1 = 0.0f;
#pragma unroll
            for (int nf = 0; nf < 8; nf++) {
                const float p0 = exp2f(sacc[mf][nf][0] - nm0);
                const float p1 = exp2f(sacc[mf][nf][1] - nm0);
                const float p2 = exp2f(sacc[mf][nf][2] - nm1);
                const float p3 = exp2f(sacc[mf][nf][3] - nm1);
                rs0 += p0 + p1;
                rs1 += p2 + p3;
                P0[mf][nf] = f2tf32(p0); P1[mf][nf] = f2tf32(p1);
                P2[mf][nf] = f2tf32(p2); P3[mf][nf] = f2tf32(p3);
            }
            rs0 += __shfl_xor_sync(0xffffffffu, rs0, 1);
            rs0 += __shfl_xor_sync(0xffffffffu, rs0, 2);
            rs1 += __shfl_xor_sync(0xffffffffu, rs1, 1);
            rs1 += __shfl_xor_sync(0xffffffffu, rs1, 2);
            lrow[mf][0] = lrow[mf][0] * al0 + rs0;
            lrow[mf][1] = lrow[mf][1] * al1 + rs1;

#pragma unroll
            for (int nf = 0; nf < 8; nf++) {
                Of[mf][nf][0] *= al0; Of[mf][nf][1] *= al0;
                Of[mf][nf][2] *= al1; Of[mf][nf][3] *= al1;
            }
        }

        // ---- O += P V ----
        const int srcA = (lane & 28) | (tig >> 1);
        const int srcB = srcA + 2;
        const bool hi  = (tig & 1);
#pragma unroll
        for (int kp = 0; kp < 4; kp++) {
            uint32_t ap[2][2][4];
#pragma unroll
            for (int mf = 0; mf < 2; mf++)
#pragma unroll
                for (int h = 0; h < 2; h++) {
                    const int kc = kp * 2 + h;
                    uint32_t x0 = __shfl_sync(0xffffffffu, P0[mf][kc], srcA);
                    uint32_t x1 = __shfl_sync(0xffffffffu, P1[mf][kc], srcA);
                    uint32_t y0 = __shfl_sync(0xffffffffu, P2[mf][kc], srcA);
                    uint32_t y1 = __shfl_sync(0xffffffffu, P3[mf][kc], srcA);
                    uint32_t z0 = __shfl_sync(0xffffffffu, P0[mf][kc], srcB);
                    uint32_t z1 = __shfl_sync(0xffffffffu, P1[mf][kc], srcB);
                    uint32_t w0 = __shfl_sync(0xffffffffu, P2[mf][kc], srcB);
                    uint32_t w1 = __shfl_sync(0xffffffffu, P3[mf][kc], srcB);
                    ap[mf][h][0] = hi ? x1 : x0;
                    ap[mf][h][1] = hi ? y1 : y0;
                    ap[mf][h][2] = hi ? z1 : z0;
                    ap[mf][h][3] = hi ? w1 : w0;
                }
#pragma unroll
            for (int half = 0; half < 2; half++) {
                uint4 vb[4];
#pragma unroll
                for (int i = 0; i < 4; i++)
                    vb[i] = *(const uint4*)&Vps[(((half * 4 + i) * 4 + kp) * 32 + lane) * 4];
#pragma unroll
                for (int h = 0; h < 2; h++)
#pragma unroll
                    for (int i = 0; i < 4; i++) {
                        uint32_t b[2];
                        b[0] = h ? vb[i].z : vb[i].x;
                        b[1] = h ? vb[i].w : vb[i].y;
                        mma_tf32(Of[0][half * 4 + i], ap[0][h], b);
                        mma_tf32(Of[1][half * 4 + i], ap[1][h], b);
                    }
            }
        }
        __syncthreads();
    }

    // Epilogue: write packed tf32 A-fragment g_Yp (quad-shuffle transform).
    const int b = bh >> 4;
    const int h = bh & 15;
    const int srcA = (lane & 28) | (tig >> 1);
    const int srcB = srcA + 2;
    const bool hi  = (tig & 1);
#pragma unroll
    for (int mf = 0; mf < 2; mf++) {
        const float inv0 = 1.0f / lrow[mf][0];
        const float inv1 = 1.0f / lrow[mf][1];
        const int mb = (b * SEQ + q0 + wid * 32 + mf * 16) >> 4;
#pragma unroll
        for (int j = 0; j < 8; j++) {
            const float n0f = Of[mf][j][0] * inv0;
            const float n1f = Of[mf][j][1] * inv0;
            const float n2f = Of[mf][j][2] * inv1;
            const float n3f = Of[mf][j][3] * inv1;
            const float x0 = __shfl_sync(0xffffffffu, n0f, srcA);
            const float x1 = __shfl_sync(0xffffffffu, n1f, srcA);
            const float y0 = __shfl_sync(0xffffffffu, n2f, srcA);
            const float y1 = __shfl_sync(0xffffffffu, n3f, srcA);
            const float z0 = __shfl_sync(0xffffffffu, n0f, srcB);
            const float z1 = __shfl_sync(0xffffffffu, n1f, srcB);
            const float w0 = __shfl_sync(0xffffffffu, n2f, srcB);
            const float w1 = __shfl_sync(0xffffffffu, n3f, srcB);
            uint4 o;
            o.x = f2tf32(hi ? x1 : x0);
            o.y = f2tf32(hi ? y1 : y0);
            o.z = f2tf32(hi ? z1 : z0);
            o.w = f2tf32(hi ? w1 : w0);
            const int slab = 2 * h + (j >> 2);
            const int kc   = j & 3;
            *(uint4*)&g_Yp[(((size_t)mb * 32 + slab) * 4 + kc) * 128 + lane * 4] = o;
        }
    }
}

// ---------------------------------------------------------------------------
extern "C" void kernel_launch(void* const* d_in, const int* in_sizes, int n_in,
                              void* d_out, int out_size)
{
    const float* x      = (const float*)d_in[0];
    const float* W_attn = (const float*)d_in[1];
    const float* b_attn = (const float*)d_in[2];
    const float* W_proj = (const float*)d_in[3];
    const float* b_proj = (const float*)d_in[4];
    float* out = (float*)d_out;

    cudaFuncSetAttribute(gemm_mma<1>, cudaFuncAttributeMaxDynamicSharedMemorySize, GEMM_SMEM);
    cudaFuncSetAttribute(gemm_mma<0>, cudaFuncAttributeMaxDynamicSharedMemorySize, GEMM_SMEM);
    cudaFuncSetAttribute(flash_mma, cudaFuncAttributeMaxDynamicSharedMemorySize, FLASH_SMEM);

    uint32_t* xp;  cudaGetSymbolAddress((void**)&xp,  g_Xp);
    uint32_t* yp;  cudaGetSymbolAddress((void**)&yp,  g_Yp);
    uint32_t* wpa; cudaGetSymbolAddress((void**)&wpa, g_Wpa);
    uint32_t* wpp; cudaGetSymbolAddress((void**)&wpp, g_Wpp);

    // 0) Pack GEMM operands
    pack_a<<<(M_TOK * D_MODEL / 4) / 256, 256>>>(x, xp);
    pack_b<<<(3 * D_MODEL * D_MODEL / 4) / 256, 256>>>(W_attn, wpa, 3 * D_MODEL);
    pack_b<<<(D_MODEL * D_MODEL / 4) / 256, 256>>>(W_proj, wpp, D_MODEL);

    // 1) QKV projection -> g_Qp/g_Kp/g_Vp (packed tf32, fused)
    {
        dim3 grid(3 * D_MODEL / 128, M_TOK / 128);  // (24, 64)
        gemm_mma<1><<<grid, 256, GEMM_SMEM>>>(xp, wpa, b_attn, nullptr);
    }
    // 2) Causal flash attention -> g_Yp (packed tf32)
    {
        dim3 grid(SEQ / QROWS, BH);  // (8, 64)
        flash_mma<<<grid, 256, FLASH_SMEM>>>();
    }
    // 3) Output projection -> d_out
    {
        dim3 grid(D_MODEL / 128, M_TOK / 128);  // (8, 64)
        gemm_mma<0><<<grid, 256, GEMM_SMEM>>>(yp, wpp, b_proj, out);
    }
}

// round 17
// speedup vs baseline: 1.9733x; 1.8000x over previous
#include <cuda_runtime.h>
#include <cuda_fp16.h>
#include <math.h>
#include <stdint.h>

// Problem constants
#define D_MODEL 1024
#define N_HEADS 16
#define HD      64
#define BATCH   4
#define SEQ     2048
#define BH      (BATCH * N_HEADS)   // 64
#define M_TOK   (BATCH * SEQ)       // 8192

// Scratch (device globals; u32 = half2)
__device__ uint32_t g_Xp[(size_t)M_TOK * D_MODEL / 2];        // x, fp16 A-frag
__device__ uint32_t g_Yp[(size_t)M_TOK * D_MODEL / 2];        // attn out, fp16 A-frag
__device__ uint32_t g_Wpa[(size_t)3 * D_MODEL * D_MODEL / 2]; // W_attn^T fp16 B-frag
__device__ uint32_t g_Wpp[(size_t)D_MODEL * D_MODEL / 2];     // W_proj^T fp16 B-frag
__device__ uint32_t g_Qp[(size_t)BH * SEQ * HD / 2];          // Q fp16 A-frag (scaled)
__device__ uint32_t g_Kp[(size_t)BH * SEQ * HD / 2];          // K fp16 B-frag (n=key)
__device__ uint32_t g_Vp[(size_t)BH * SEQ * HD / 2];          // V fp16 B-frag (n=d)

// ---------------------------------------------------------------------------
// Helpers
// ---------------------------------------------------------------------------
__device__ __forceinline__ uint32_t h2u(float a, float b) {
    __half2 h = __floats2half2_rn(a, b);
    return *reinterpret_cast<uint32_t*>(&h);
}
__device__ __forceinline__ void mma_f16(float d[4], const uint32_t a[4],
                                        const uint32_t b[2]) {
    asm volatile(
        "mma.sync.aligned.m16n8k16.row.col.f32.f16.f16.f32 "
        "{%0,%1,%2,%3}, {%4,%5,%6,%7}, {%8,%9}, {%0,%1,%2,%3};"
        : "+f"(d[0]), "+f"(d[1]), "+f"(d[2]), "+f"(d[3])
        : "r"(a[0]), "r"(a[1]), "r"(a[2]), "r"(a[3]), "r"(b[0]), "r"(b[1]));
}
__device__ __forceinline__ uint32_t smem_u32(const void* p) {
    uint32_t a;
    asm("{ .reg .u64 t; cvta.to.shared.u64 t, %1; cvt.u32.u64 %0, t; }"
        : "=r"(a) : "l"(p));
    return a;
}
#define CP16(dst, src) \
    asm volatile("cp.async.cg.shared.global [%0], [%1], 16;" \
                 :: "r"(dst), "l"(src) : "memory")
#define CPCOMMIT() asm volatile("cp.async.commit_group;" ::: "memory")
#define CPWAIT1()  asm volatile("cp.async.wait_group 1;" ::: "memory")
#define CPWAIT0()  asm volatile("cp.async.wait_group 0;" ::: "memory")

// ---------------------------------------------------------------------------
// Packing kernels (fp16).
// A-frag uint4 i: lane(5) | ks(1) | slab(5) | mb : rows 16mb+g (+8),
//   k0 = 32slab+16ks+2t; uint4 = {h2(r0 k0,k0+1), h2(r1 ..), h2(r0 k0+8,k0+9), h2(r1 ..)}
// B-frag uint4 i: lane(5) | slab(5) | nb : n = 8nb+g, k0 = 32slab+2t;
//   uint4 = {h2(k0,k0+1), h2(k0+8,k0+9), h2(k0+16,k0+17), h2(k0+24,k0+25)} (all W^T[n][k])
// ---------------------------------------------------------------------------
__global__ void pack_a(const float* __restrict__ X, uint32_t* __restrict__ Xp)
{
    const int i    = blockIdx.x * 256 + threadIdx.x;
    const int lane = i & 31, ks = (i >> 5) & 1, slab = (i >> 6) & 31, mb = i >> 11;
    const int g = lane >> 2, t = lane & 3;
    const float* r0 = X + (size_t)(mb * 16 + g) * D_MODEL + slab * 32 + ks * 16 + 2 * t;
    const float* r1 = r0 + 8 * D_MODEL;
    float2 x0 = *(const float2*)r0;
    float2 x1 = *(const float2*)r1;
    float2 y0 = *(const float2*)(r0 + 8);
    float2 y1 = *(const float2*)(r1 + 8);
    uint4 o;
    o.x = h2u(x0.x, x0.y);
    o.y = h2u(x1.x, x1.y);
    o.z = h2u(y0.x, y0.y);
    o.w = h2u(y1.x, y1.y);
    *(uint4*)&Xp[(size_t)i * 4] = o;
}

__global__ void pack_b(const float* __restrict__ W, uint32_t* __restrict__ Wp, int N)
{
    const int i    = blockIdx.x * 256 + threadIdx.x;
    const int lane = i & 31, slab = (i >> 5) & 31, nb = i >> 10;
    const int g = lane >> 2, t = lane & 3;
    const int n  = nb * 8 + g;
    const int k0 = slab * 32 + 2 * t;
    const float* p = W + (size_t)k0 * N + n;
    const size_t s = N;
    uint4 o;
    o.x = h2u(p[0],       p[s]);
    o.y = h2u(p[8 * s],   p[9 * s]);
    o.z = h2u(p[16 * s],  p[17 * s]);
    o.w = h2u(p[24 * s],  p[25 * s]);
    *(uint4*)&Wp[(size_t)i * 4] = o;
}

// ---------------------------------------------------------------------------
// FP16 GEMM, cp.async 2-stage. CTA 128x128, 8 warps (4M x 2N), warp 32x64.
// Slab k=32 = 2 ksteps of m16n8k16. Stage = A 8KB + B 8KB.
// MODE 1: fused-pack epilogue -> g_Qp/g_Kp/g_Vp (fp16 fragment layouts).
// MODE 0: fp32 out + bias.
// ---------------------------------------------------------------------------
#define GEMM_SMEM 32768

template <int MODE>
__global__ void __launch_bounds__(256, 2)
gemm_mma(const uint32_t* __restrict__ Apk, const uint32_t* __restrict__ Bpk,
         const float* __restrict__ bias, float* __restrict__ Cout)
{
    constexpr int NS = 32;
    extern __shared__ uint32_t sm[];
    const uint4* sm4 = (const uint4*)sm;
    const int tid  = threadIdx.x;
    const int wid  = tid >> 5;
    const int lane = tid & 31;
    const int g    = lane >> 2;
    const int tig  = lane & 3;
    const int m0   = blockIdx.y * 128;
    const int n0   = blockIdx.x * 128;
    const int mb0  = m0 >> 4;   // 16-row blocks
    const int nb0  = n0 >> 3;   // 8-col blocks
    const uint32_t smb = smem_u32(sm);

    float acc[2][8][4];
#pragma unroll
    for (int mf = 0; mf < 2; mf++)
#pragma unroll
        for (int nf = 0; nf < 8; nf++)
#pragma unroll
            for (int r = 0; r < 4; r++) acc[mf][nf][r] = 0.0f;

    // Copy maps: 2 A-chunks + 2 B-chunks (16B) per thread per slab.
    uint32_t asrc[2], bsrc[2], adst[2], bdst[2];
#pragma unroll
    for (int c = 0; c < 2; c++) {
        const int ci = c * 256 + tid;      // 0..511
        asrc[c] = ((uint32_t)(mb0 + (ci >> 6)) * 2048u + (uint32_t)(ci & 63)) * 4u;
        bsrc[c] = ((uint32_t)(nb0 + (ci >> 5)) * 1024u + (uint32_t)(ci & 31)) * 4u;
        adst[c] = smb + (uint32_t)ci * 16u;
        bdst[c] = smb + 8192u + (uint32_t)ci * 16u;
    }

    auto issue = [&](int s, int buf) {
        const uint32_t so = (uint32_t)buf * 16384u;
#pragma unroll
        for (int c = 0; c < 2; c++)
            CP16(adst[c] + so, (const void*)(Apk + asrc[c] + (uint32_t)s * 256u));
#pragma unroll
        for (int c = 0; c < 2; c++)
            CP16(bdst[c] + so, (const void*)(Bpk + bsrc[c] + (uint32_t)s * 128u));
        CPCOMMIT();
    };

    issue(0, 0);

    const int wm2 = (wid & 3) * 2;
    const int wn8 = (wid >> 2) * 8;

    for (int s = 0; s < NS; s++) {
        if (s + 1 < NS) { issue(s + 1, (s + 1) & 1); CPWAIT1(); }
        else            { CPWAIT0(); }
        __syncthreads();

        const uint4* Ab = sm4 + (uint32_t)(s & 1) * 1024u;   // uint4 units
        const uint4* Bb = Ab + 512;

        uint4 af[2][2];
#pragma unroll
        for (int mf = 0; mf < 2; mf++)
#pragma unroll
            for (int ks = 0; ks < 2; ks++)
                af[mf][ks] = Ab[(wm2 + mf) * 64 + ks * 32 + lane];
#pragma unroll
        for (int nf = 0; nf < 8; nf++) {
            const uint4 bv = Bb[(wn8 + nf) * 32 + lane];
#pragma unroll
            for (int ks = 0; ks < 2; ks++) {
                uint32_t b2[2];
                b2[0] = ks ? bv.z : bv.x;
                b2[1] = ks ? bv.w : bv.y;
                mma_f16(acc[0][nf], (const uint32_t*)&af[0][ks], b2);
                mma_f16(acc[1][nf], (const uint32_t*)&af[1][ks], b2);
            }
        }
        __syncthreads();
    }

    if (MODE == 0) {
#pragma unroll
        for (int mf = 0; mf < 2; mf++) {
            const int row0 = m0 + (wid & 3) * 32 + mf * 16 + g;
#pragma unroll
            for (int nf = 0; nf < 8; nf++) {
                const int col = n0 + (wid >> 2) * 64 + nf * 8 + 2 * tig;
                const float2 bv = *(const float2*)(bias + col);
                *(float2*)(Cout + (size_t)row0 * D_MODEL + col) =
                    make_float2(acc[mf][nf][0] + bv.x, acc[mf][nf][1] + bv.y);
                *(float2*)(Cout + (size_t)(row0 + 8) * D_MODEL + col) =
                    make_float2(acc[mf][nf][2] + bv.x, acc[mf][nf][3] + bv.y);
            }
        }
    } else {
        // Fused pack into fp16 fragment layouts.
        const float QSCALE = 0.125f * 1.44269504f;
        const int colbase = n0 + (wid >> 2) * 64;   // one head
        const int which = colbase >> 10;            // 0=Q 1=K 2=V
        const int h     = (colbase & 1023) >> 6;

#pragma unroll
        for (int mf = 0; mf < 2; mf++) {
            const int mbase = m0 + (wid & 3) * 32 + mf * 16;
            const int b  = mbase >> 11;
            const int tb = mbase & 2047;
            const int bh = b * N_HEADS + h;

            float v0[8], v1[8], v2[8], v3[8];
#pragma unroll
            for (int nf = 0; nf < 8; nf++) {
                const int col = colbase + nf * 8 + 2 * tig;
                const float2 bv = *(const float2*)(bias + col);
                v0[nf] = acc[mf][nf][0] + bv.x;
                v1[nf] = acc[mf][nf][1] + bv.y;
                v2[nf] = acc[mf][nf][2] + bv.x;
                v3[nf] = acc[mf][nf][3] + bv.y;
            }

            if (which == 0) {
                // A-frag (lane-local), QSCALE folded.
                const int qt = tb >> 8, mb = (tb >> 4) & 15;
                uint4* base = (uint4*)g_Qp
                    + (size_t)(((bh * 8 + qt) * 16 + mb) * 4) * 32 + lane;
#pragma unroll
                for (int ks = 0; ks < 4; ks++) {
                    uint4 o;
                    o.x = h2u(v0[2 * ks] * QSCALE,     v1[2 * ks] * QSCALE);
                    o.y = h2u(v2[2 * ks] * QSCALE,     v3[2 * ks] * QSCALE);
                    o.z = h2u(v0[2 * ks + 1] * QSCALE, v1[2 * ks + 1] * QSCALE);
                    o.w = h2u(v2[2 * ks + 1] * QSCALE, v3[2 * ks + 1] * QSCALE);
                    base[(size_t)ks * 32] = o;
                }
            } else if (which == 1) {
                // K B-frag (lane-local): key = 8nfk+g, uint4 covers 2 ksteps.
                const int kt = tb >> 6;
                const int nfk0 = (tb & 63) >> 3;
                uint4* base = (uint4*)g_Kp
                    + (size_t)((bh * 32 + kt) * 16) * 32 + lane;
#pragma unroll
                for (int rb = 0; rb < 2; rb++) {
                    const float* va = rb ? v2 : v0;
                    const float* vb = rb ? v3 : v1;
#pragma unroll
                    for (int kp2 = 0; kp2 < 2; kp2++) {
                        uint4 o;
                        o.x = h2u(va[4 * kp2],     vb[4 * kp2]);
                        o.y = h2u(va[4 * kp2 + 1], vb[4 * kp2 + 1]);
                        o.z = h2u(va[4 * kp2 + 2], vb[4 * kp2 + 2]);
                        o.w = h2u(va[4 * kp2 + 3], vb[4 * kp2 + 3]);
                        base[(size_t)(((nfk0 + rb) * 2 + kp2)) * 32] = o;
                    }
                }
            } else {
                // V B-frag (n=d, k=key): cross-quad transpose shuffle.
                const int kt = tb >> 6;
                const int ks = (tb >> 4) & 3;
                const int kp2 = ks >> 1, pos = ks & 1;
                const int LA = 8 * tig + (g >> 1);
                const int LB = LA + 4;
                const bool gp = (g & 1);
                uint32_t* vbase = g_Vp + (size_t)((bh * 32 + kt) * 16) * 128
                                + (size_t)kp2 * 128 + lane * 4 + pos * 2;
#pragma unroll
                for (int nfd = 0; nfd < 8; nfd++) {
                    const float a0 = __shfl_sync(0xffffffffu, v0[nfd], LA);
                    const float a1 = __shfl_sync(0xffffffffu, v1[nfd], LA);
                    const float a2 = __shfl_sync(0xffffffffu, v2[nfd], LA);
                    const float a3 = __shfl_sync(0xffffffffu, v3[nfd], LA);
                    const float b0 = __shfl_sync(0xffffffffu, v0[nfd], LB);
                    const float b1 = __shfl_sync(0xffffffffu, v1[nfd], LB);
                    const float b2 = __shfl_sync(0xffffffffu, v2[nfd], LB);
                    const float b3 = __shfl_sync(0xffffffffu, v3[nfd], LB);
                    uint2 o;
                    o.x = h2u(gp ? a1 : a0, gp ? b1 : b0);   // keys 2t, 2t+1
                    o.y = h2u(gp ? a3 : a2, gp ? b3 : b2);   // keys 2t+8, 2t+9
                    *(uint2*)(vbase + (size_t)nfd * 256) = o;
                }
            }
        }
    }
}

// ---------------------------------------------------------------------------
// Flash attention, fp16 mma. CTA 256 q-rows, 8 warps x 32 rows.
// Q staged once (32KB); K/V per 64-key tile (8KB each), 2-stage cp.async.
// P A-fragments are LANE-LOCAL (fp16 acc layout == A layout): no shuffles.
// Smem: 32KB Q + 2 x 16KB = 64KB.
// ---------------------------------------------------------------------------
#define QROWS 256
#define QP4 2048                          // Q uint4 count (32KB)
#define KVT4 1024                         // one KV stage uint4 count (16KB)
#define FLASH_SMEM ((QP4 + 2 * KVT4) * 16)   // 65536

__global__ void __launch_bounds__(256, 1)
flash_mma()
{
    extern __shared__ uint32_t fsm[];
    const uint4* fsm4 = (const uint4*)fsm;
    const uint32_t smb = smem_u32(fsm);

    const int tid  = threadIdx.x;
    const int wid  = tid >> 5;
    const int lane = tid & 31;
    const int g    = lane >> 2;
    const int tig  = lane & 3;
    const int qt   = (int)gridDim.x - 1 - (int)blockIdx.x;
    const int bh   = blockIdx.y;
    const int q0   = qt * QROWS;
    const int nt   = qt * 4 + 4;

    const uint32_t* qg = g_Qp + (size_t)(bh * 8 + qt) * (QP4 * 4);
    const uint32_t* kg = g_Kp + (size_t)bh * 32 * 2048;   // 512 uint4 per tile
    const uint32_t* vg = g_Vp + (size_t)bh * 32 * 2048;

    // Q copy (one group, retires first)
#pragma unroll
    for (int c = 0; c < 8; c++)
        CP16(smb + (uint32_t)(c * 256 + tid) * 16u,
             (const void*)(qg + (size_t)(c * 256 + tid) * 4));
    CPCOMMIT();

    auto issueKV = [&](int kt, int buf) {
        const uint32_t so = smb + (uint32_t)(QP4 + buf * KVT4) * 16u;
        const uint32_t* ks = kg + (size_t)kt * 2048;
        const uint32_t* vs = vg + (size_t)kt * 2048;
#pragma unroll
        for (int c = 0; c < 2; c++)
            CP16(so + (uint32_t)(c * 256 + tid) * 16u,
                 (const void*)(ks + (size_t)(c * 256 + tid) * 4));
#pragma unroll
        for (int c = 0; c < 2; c++)
            CP16(so + 8192u + (uint32_t)(c * 256 + tid) * 16u,
                 (const void*)(vs + (size_t)(c * 256 + tid) * 4));
        CPCOMMIT();
    };

    issueKV(0, 0);

    float mrow[2][2], lrow[2][2], Of[2][8][4];
#pragma unroll
    for (int mf = 0; mf < 2; mf++) {
        mrow[mf][0] = mrow[mf][1] = -1e30f;
        lrow[mf][0] = lrow[mf][1] = 0.0f;
#pragma unroll
        for (int nf = 0; nf < 8; nf++)
#pragma unroll
            for (int r = 0; r < 4; r++) Of[mf][nf][r] = 0.0f;
    }

    for (int kt = 0; kt < nt; kt++) {
        if (kt + 1 < nt) { issueKV(kt + 1, (kt + 1) & 1); CPWAIT1(); }
        else             { CPWAIT0(); }
        __syncthreads();

        const uint4* Ks4 = fsm4 + QP4 + (kt & 1) * KVT4;
        const uint4* Vs4 = Ks4 + 512;

        // ---- S = Q K^T  (k = d = 64: 4 ksteps of 16) ----
        float sacc[2][8][4];
#pragma unroll
        for (int mf = 0; mf < 2; mf++)
#pragma unroll
            for (int nf = 0; nf < 8; nf++)
#pragma unroll
                for (int r = 0; r < 4; r++) sacc[mf][nf][r] = 0.0f;

#pragma unroll
        for (int kp2 = 0; kp2 < 2; kp2++) {
            uint4 kb[8];
#pragma unroll
            for (int nf = 0; nf < 8; nf++)
                kb[nf] = Ks4[(nf * 2 + kp2) * 32 + lane];
#pragma unroll
            for (int h = 0; h < 2; h++) {
                const int ks = kp2 * 2 + h;
                uint4 aq[2];
#pragma unroll
                for (int mf = 0; mf < 2; mf++)
                    aq[mf] = fsm4[((wid * 2 + mf) * 4 + ks) * 32 + lane];
#pragma unroll
                for (int nf = 0; nf < 8; nf++) {
                    uint32_t b2[2];
                    b2[0] = h ? kb[nf].z : kb[nf].x;
                    b2[1] = h ? kb[nf].w : kb[nf].y;
                    mma_f16(sacc[0][nf], (const uint32_t*)&aq[0], b2);
                    mma_f16(sacc[1][nf], (const uint32_t*)&aq[1], b2);
                }
            }
        }

        // Causal mask
        if (kt >= nt - 4) {
            const int n0 = kt * 64;
#pragma unroll
            for (int mf = 0; mf < 2; mf++) {
                const int r0g = q0 + wid * 32 + mf * 16 + g;
#pragma unroll
                for (int nf = 0; nf < 8; nf++) {
                    const int c0 = n0 + nf * 8 + 2 * tig;
                    if (c0     > r0g)     sacc[mf][nf][0] = -1e30f;
                    if (c0 + 1 > r0g)     sacc[mf][nf][1] = -1e30f;
                    if (c0     > r0g + 8) sacc[mf][nf][2] = -1e30f;
                    if (c0 + 1 > r0g + 8) sacc[mf][nf][3] = -1e30f;
                }
            }
        }

        // ---- Online softmax; P packed lane-locally into fp16 A-frags ----
        uint4 Pa[2][4];
#pragma unroll
        for (int mf = 0; mf < 2; mf++) {
            float rm0 = -1e30f, rm1 = -1e30f;
#pragma unroll
            for (int nf = 0; nf < 8; nf++) {
                rm0 = fmaxf(rm0, fmaxf(sacc[mf][nf][0], sacc[mf][nf][1]));
                rm1 = fmaxf(rm1, fmaxf(sacc[mf][nf][2], sacc[mf][nf][3]));
            }
            rm0 = fmaxf(rm0, __shfl_xor_sync(0xffffffffu, rm0, 1));
            rm0 = fmaxf(rm0, __shfl_xor_sync(0xffffffffu, rm0, 2));
            rm1 = fmaxf(rm1, __shfl_xor_sync(0xffffffffu, rm1, 1));
            rm1 = fmaxf(rm1, __shfl_xor_sync(0xffffffffu, rm1, 2));

            const float nm0 = fmaxf(mrow[mf][0], rm0);
            const float nm1 = fmaxf(mrow[mf][1], rm1);
            const float al0 = exp2f(mrow[mf][0] - nm0);
            const float al1 = exp2f(mrow[mf][1] - nm1);
            mrow[mf][0] = nm0; mrow[mf][1] = nm1;

            float rs0 = 0.0f, rs1 = 0.0f;
#pragma unroll
            for (int ks = 0; ks < 4; ks++) {
                const int nA = 2 * ks, nB = 2 * ks + 1;
                const float pA0 = exp2f(sacc[mf][nA][0] - nm0);
                const float pA1 = exp2f(sacc[mf][nA][1] - nm0);
                const float pA2 = exp2f(sacc[mf][nA][2] - nm1);
                const float pA3 = exp2f(sacc[mf][nA][3] - nm1);
                const float pB0 = exp2f(sacc[mf][nB][0] - nm0);
                const float pB1 = exp2f(sacc[mf][nB][1] - nm0);
                const float pB2 = exp2f(sacc[mf][nB][2] - nm1);
                const float pB3 = exp2f(sacc[mf][nB][3] - nm1);
                rs0 += pA0 + pA1 + pB0 + pB1;
                rs1 += pA2 + pA3 + pB2 + pB3;
                Pa[mf][ks].x = h2u(pA0, pA1);
                Pa[mf][ks].y = h2u(pA2, pA3);
                Pa[mf][ks].z = h2u(pB0, pB1);
                Pa[mf][ks].w = h2u(pB2, pB3);
            }
            rs0 += __shfl_xor_sync(0xffffffffu, rs0, 1);
            rs0 += __shfl_xor_sync(0xffffffffu, rs0, 2);
            rs1 += __shfl_xor_sync(0xffffffffu, rs1, 1);
            rs1 += __shfl_xor_sync(0xffffffffu, rs1, 2);
            lrow[mf][0] = lrow[mf][0] * al0 + rs0;
            lrow[mf][1] = lrow[mf][1] * al1 + rs1;

#pragma unroll
            for (int nf = 0; nf < 8; nf++) {
                Of[mf][nf][0] *= al0; Of[mf][nf][1] *= al0;
                Of[mf][nf][2] *= al1; Of[mf][nf][3] *= al1;
            }
        }

        // ---- O += P V  (k = keys = 64: 4 ksteps) ----
#pragma unroll
        for (int kp2 = 0; kp2 < 2; kp2++) {
            uint4 vb[8];
#pragma unroll
            for (int nf = 0; nf < 8; nf++)
                vb[nf] = Vs4[(nf * 2 + kp2) * 32 + lane];
#pragma unroll
            for (int h = 0; h < 2; h++) {
                const int ks = kp2 * 2 + h;
#pragma unroll
                for (int nf = 0; nf < 8; nf++) {
                    uint32_t b2[2];
                    b2[0] = h ? vb[nf].z : vb[nf].x;
                    b2[1] = h ? vb[nf].w : vb[nf].y;
                    mma_f16(Of[0][nf], (const uint32_t*)&Pa[0][ks], b2);
                    mma_f16(Of[1][nf], (const uint32_t*)&Pa[1][ks], b2);
                }
            }
        }
        __syncthreads();
    }

    // Epilogue: normalized Of -> g_Yp fp16 A-frag (lane-local, no shuffles).
    const int b = bh >> 4;
    const int h = bh & 15;
#pragma unroll
    for (int mf = 0; mf < 2; mf++) {
        const float inv0 = 1.0f / lrow[mf][0];
        const float inv1 = 1.0f / lrow[mf][1];
        const int mb = (b * SEQ + q0 + wid * 32 + mf * 16) >> 4;
        float y0[8], y1[8], y2[8], y3[8];
#pragma unroll
        for (int nf = 0; nf < 8; nf++) {
            y0[nf] = Of[mf][nf][0] * inv0;
            y1[nf] = Of[mf][nf][1] * inv0;
            y2[nf] = Of[mf][nf][2] * inv1;
            y3[nf] = Of[mf][nf][3] * inv1;
        }
#pragma unroll
        for (int sl = 0; sl < 2; sl++)
#pragma unroll
            for (int ks = 0; ks < 2; ks++) {
                const int j = sl * 2 + ks;
                uint4 o;
                o.x = h2u(y0[2 * j],     y1[2 * j]);
                o.y = h2u(y2[2 * j],     y3[2 * j]);
                o.z = h2u(y0[2 * j + 1], y1[2 * j + 1]);
                o.w = h2u(y2[2 * j + 1], y3[2 * j + 1]);
                *(uint4*)&g_Yp[((((size_t)mb * 32 + 2 * h + sl) * 2 + ks) * 32
                                + lane) * 4] = o;
            }
    }
}

// ---------------------------------------------------------------------------
extern "C" void kernel_launch(void* const* d_in, const int* in_sizes, int n_in,
                              void* d_out, int out_size)
{
    const float* x      = (const float*)d_in[0];
    const float* W_attn = (const float*)d_in[1];
    const float* b_attn = (const float*)d_in[2];
    const float* W_proj = (const float*)d_in[3];
    const float* b_proj = (const float*)d_in[4];
    float* out = (float*)d_out;

    cudaFuncSetAttribute(gemm_mma<1>, cudaFuncAttributeMaxDynamicSharedMemorySize, GEMM_SMEM);
    cudaFuncSetAttribute(gemm_mma<0>, cudaFuncAttributeMaxDynamicSharedMemorySize, GEMM_SMEM);
    cudaFuncSetAttribute(flash_mma, cudaFuncAttributeMaxDynamicSharedMemorySize, FLASH_SMEM);

    uint32_t* xp;  cudaGetSymbolAddress((void**)&xp,  g_Xp);
    uint32_t* yp;  cudaGetSymbolAddress((void**)&yp,  g_Yp);
    uint32_t* wpa; cudaGetSymbolAddress((void**)&wpa, g_Wpa);
    uint32_t* wpp; cudaGetSymbolAddress((void**)&wpp, g_Wpp);

    // 0) Pack GEMM operands (fp16 fragment layouts)
    // pack_a total uint4 = (M_TOK/16) * 2048 = 1,048,576 -> 4096 blocks
    pack_a<<<(M_TOK / 16) * 2048 / 256, 256>>>(x, xp);
    // pack_b total uint4 = (N/8) * 1024
    pack_b<<<(3 * D_MODEL / 8) * 1024 / 256, 256>>>(W_attn, wpa, 3 * D_MODEL);
    pack_b<<<(D_MODEL / 8) * 1024 / 256, 256>>>(W_proj, wpp, D_MODEL);

    // 1) QKV projection -> g_Qp/g_Kp/g_Vp (fp16 fused pack)
    {
        dim3 grid(3 * D_MODEL / 128, M_TOK / 128);  // (24, 64)
        gemm_mma<1><<<grid, 256, GEMM_SMEM>>>(xp, wpa, b_attn, nullptr);
    }
    // 2) Causal flash attention -> g_Yp (fp16 packed)
    {
        dim3 grid(SEQ / QROWS, BH);  // (8, 64)
        flash_mma<<<grid, 256, FLASH_SMEM>>>();
    }
    // 3) Output projection -> d_out (fp32)
    {
        dim3 grid(D_MODEL / 128, M_TOK / 128);  // (8, 64)
        gemm_mma<0><<<grid, 256, GEMM_SMEM>>>(yp, wpp, b_proj, out);
    }
}